// round 12
// baseline (speedup 1.0000x reference)
#include <cuda_runtime.h>
#include <cstddef>

#define BB 4
#define LL 2048
#define HH 8
#define DD 64
#define SK 40
#define NT 40
#define BHN 32
#define NSPLIT 16
#define CHUNK 128
#define KTPAD 132
#define SCALE 0.125f

#define CK 384
#define NKC 6
#define LQ 4

// ---------------- scratch ----------------
__device__ int   g_sorted[LL * SK];
__device__ int   g_bnd[LL * 8];
__device__ float g_M[BHN * LL];
__device__ int   g_top[BHN * NT];
__device__ float g_pm[BHN * NSPLIT * NT];
__device__ float g_pl[BHN * NSPLIT * NT];
__device__ float g_po[BHN * NSPLIT * NT * DD];
__device__ int   g_cnt1[BHN];
__device__ int   g_cnt2[BHN];

// ================= kernel 0: prep — sort indices per l, strip boundaries =================
__global__ void prep_kernel(const void* __restrict__ idxbuf) {
    __shared__ int s_is64;
    int t = threadIdx.x;
    if (t < 32) {
        long long v = ((const long long*)idxbuf)[t];
        int ok = (v >= 0 && v < LL);
        unsigned m = __ballot_sync(0xffffffffu, ok);
        if (t == 0) s_is64 = (m == 0xffffffffu);
    }
    __syncthreads();
    int l = blockIdx.x * 256 + t;      // 8 blocks x 256 = 2048

    int arr[SK];
    if (s_is64) {
        const long long* p = (const long long*)idxbuf + (long long)l * SK;
#pragma unroll
        for (int i = 0; i < SK; i++) arr[i] = (int)p[i];
    } else {
        const int* p = (const int*)idxbuf + l * SK;
#pragma unroll
        for (int i = 0; i < SK; i++) arr[i] = p[i];
    }
    for (int i = 1; i < SK; i++) {
        int key = arr[i], j = i - 1;
        while (j >= 0 && arr[j] > key) { arr[j + 1] = arr[j]; j--; }
        arr[j + 1] = key;
    }
#pragma unroll
    for (int i = 0; i < SK; i++) g_sorted[l * SK + i] = arr[i];
    int pos = 0;
#pragma unroll
    for (int kc = 0; kc <= NKC; kc++) {
        while (pos < SK && arr[pos] < kc * CK) pos++;
        g_bnd[(l << 3) + kc] = pos;
    }
}

// ================= kernel 1: sample_m v7 (smem strips, sorted ranges) + fused topk ======
__global__ void __launch_bounds__(256, 2)
sample_m_kernel(const float* __restrict__ Q, const float* __restrict__ K) {
    extern __shared__ float smem[];
    float* Ks    = smem;               // CK*64 = 24576 floats (96 KB)
    float* accMx = Ks + CK * DD;       // 512
    float* accSm = accMx + 512;        // 512
    __shared__ int s_last;

    int bid = blockIdx.x;
    int bh = bid >> 2, lq = bid & 3;
    int b = bh >> 3, h = bh & 7;
    int t = threadIdx.x;
    int w = t >> 5, lane = t & 31;
    int g = lane >> 3, li = lane & 7;

    for (int i = t; i < 512; i += 256) { accMx[i] = -3e38f; accSm[i] = 0.f; }

    for (int kc = 0; kc < NKC; kc++) {
        __syncthreads();
        int lo = kc * CK;
        int rows = min(CK, LL - lo);
        for (int i = t; i < rows * 16; i += 256) {
            int rr = i >> 4, c4 = i & 15;
            ((float4*)Ks)[(rr << 4) + c4] =
                ((const float4*)K)[(((size_t)(b * LL + lo + rr) * HH + h) << 4) + c4];
        }
        __syncthreads();

        int lbase = lq * 512 + w * 64;
        for (int ll = 0; ll < 64; ll++) {
            int l = lbase + ll;
            int p0 = g_bnd[(l << 3) + kc];
            int p1 = g_bnd[(l << 3) + kc + 1];
            if (p0 == p1) continue;

            const float* qb = Q + (((size_t)(b * LL + l) * HH + h) << 6) + (li << 3);
            float4 qa = ((const float4*)qb)[0];
            float4 qz = ((const float4*)qb)[1];
            const int* sp = g_sorted + l * SK;

            float mx = -3e38f, sm = 0.f;
            for (int p = p0; p < p1; p += 4) {
                int hh = p + g;
                int act = (hh < p1);
                int j = sp[act ? hh : p0];        // group-uniform broadcast load
                int jl = j - lo;
                const float4* kp = (const float4*)(Ks + (jl << 6) + (li << 3));
                float4 k0 = kp[0];
                float4 k1 = kp[1];
                float v = qa.x * k0.x;
                v = fmaf(qa.y, k0.y, v);
                v = fmaf(qa.z, k0.z, v);
                v = fmaf(qa.w, k0.w, v);
                v = fmaf(qz.x, k1.x, v);
                v = fmaf(qz.y, k1.y, v);
                v = fmaf(qz.z, k1.z, v);
                v = fmaf(qz.w, k1.w, v);
                v += __shfl_xor_sync(0xffffffffu, v, 1);
                v += __shfl_xor_sync(0xffffffffu, v, 2);
                v += __shfl_xor_sync(0xffffffffu, v, 4);
                if (act) { mx = fmaxf(mx, v); sm += v; }
            }
            mx = fmaxf(mx, __shfl_xor_sync(0xffffffffu, mx, 8));
            mx = fmaxf(mx, __shfl_xor_sync(0xffffffffu, mx, 16));
            sm += __shfl_xor_sync(0xffffffffu, sm, 8);
            sm += __shfl_xor_sync(0xffffffffu, sm, 16);
            if (lane == 0) {
                int a = w * 64 + ll;
                accMx[a] = fmaxf(accMx[a], mx);
                accSm[a] += sm;
            }
        }
    }
    __syncthreads();
    for (int i = t; i < 512; i += 256)
        g_M[bh * LL + lq * 512 + i] = accMx[i] - accSm[i] * (1.0f / (float)LL);

    // ---- fused topk: last of the 4 lq-blocks of this bh ----
    __threadfence();
    if (t == 0) s_last = (atomicAdd(&g_cnt1[bh], 1) == LQ - 1) ? 1 : 0;
    __syncthreads();
    if (!s_last) return;

    if (t < 32) {
        float* sM = Ks;    // reuse strip buffer (2048 floats)
        for (int i = lane; i < LL; i += 32) sM[i] = g_M[bh * LL + i];
        __syncwarp();

        int base = lane << 6;
        unsigned long long s0 = 0ull, s1 = 0ull, s2 = 0ull;
#pragma unroll 4
        for (int i = 0; i < 64; i++) {
            float x = sM[base + i];
            unsigned uv = __float_as_uint(x);
            uv ^= (uv >> 31) ? 0xffffffffu : 0x80000000u;
            unsigned long long k = ((unsigned long long)uv << 32)
                                 | (unsigned)(LL - 1 - (base + i));
            if (k > s0)      { s2 = s1; s1 = s0; s0 = k; }
            else if (k > s1) { s2 = s1; s1 = k; }
            else if (k > s2) { s2 = k; }
        }
        for (int it = 0; it < NT; it++) {
            unsigned ord0 = (unsigned)(s0 >> 32);
            unsigned m1 = __reduce_max_sync(0xffffffffu, ord0);
            unsigned lowp = (ord0 == m1) ? ((unsigned)s0 + 1u) : 0u;
            unsigned m2 = __reduce_max_sync(0xffffffffu, lowp);
            int wi = LL - (int)m2;
            if (lane == 0) g_top[bh * NT + it] = wi;
            if (lane == (wi >> 6)) {
                sM[wi] = -3e38f;
                s0 = s1; s1 = s2; s2 = 0ull;
                if (s0 == 0ull) {
                    for (int i = 0; i < 64; i++) {
                        float x = sM[base + i];
                        unsigned uv = __float_as_uint(x);
                        uv ^= (uv >> 31) ? 0xffffffffu : 0x80000000u;
                        unsigned long long k = ((unsigned long long)uv << 32)
                                             | (unsigned)(LL - 1 - (base + i));
                        if (k > s0)      { s2 = s1; s1 = s0; s0 = k; }
                        else if (k > s1) { s2 = s1; s1 = k; }
                        else if (k > s2) { s2 = k; }
                    }
                }
            }
            __syncwarp();
        }
        if (lane == 0) g_cnt1[bh] = 0;
    }
}

// ================= kernel 2: attn (R11-proven) + fused combine =================
__global__ void __launch_bounds__(256, 3)
attn_kernel(const float* __restrict__ Q,
            const float* __restrict__ K,
            const float* __restrict__ V,
            float* __restrict__ out) {
    extern __shared__ float smem[];
    __shared__ int s_last;
    int bh = blockIdx.x / NSPLIT, split = blockIdx.x % NSPLIT;
    int b = bh >> 3, h = bh & 7;
    int t = threadIdx.x;

    float* Qs = smem;
    float* KV = Qs + NT * DD;
    float* Ss = KV + 64 * KTPAD;

    for (int i = t; i < NT * 16; i += 256) {
        int u = i >> 4, c = i & 15;
        int ql = g_top[bh * NT + u];
        ((float4*)Qs)[i] =
            ((const float4*)Q)[(((size_t)(b * LL + ql) * HH + h) << 4) + c];
    }
    int key0 = split * CHUNK;
    for (int i = t; i < CHUNK * DD; i += 256) {
        int j = i >> 6, d = i & 63;
        KV[d * KTPAD + j] = K[(((size_t)(b * LL + key0 + j) * HH + h) << 6) + d];
    }
    __syncthreads();

    {
        int ublk = t >> 5;
        int jg   = t & 31;
        float4 acc[5];
#pragma unroll
        for (int k = 0; k < 5; k++) acc[k] = make_float4(0.f, 0.f, 0.f, 0.f);
        const float4* Kt4 = (const float4*)KV;
#pragma unroll 4
        for (int d = 0; d < 64; d += 4) {
            float4 kv0 = Kt4[(d + 0) * 33 + jg];
            float4 kv1 = Kt4[(d + 1) * 33 + jg];
            float4 kv2 = Kt4[(d + 2) * 33 + jg];
            float4 kv3 = Kt4[(d + 3) * 33 + jg];
#pragma unroll
            for (int k = 0; k < 5; k++) {
                float4 qv = *(const float4*)(Qs + (ublk * 5 + k) * 64 + d);
                acc[k].x += qv.x * kv0.x;
                acc[k].y += qv.x * kv0.y;
                acc[k].z += qv.x * kv0.z;
                acc[k].w += qv.x * kv0.w;
                acc[k].x += qv.y * kv1.x;
                acc[k].y += qv.y * kv1.y;
                acc[k].z += qv.y * kv1.z;
                acc[k].w += qv.y * kv1.w;
                acc[k].x += qv.z * kv2.x;
                acc[k].y += qv.z * kv2.y;
                acc[k].z += qv.z * kv2.z;
                acc[k].w += qv.z * kv2.w;
                acc[k].x += qv.w * kv3.x;
                acc[k].y += qv.w * kv3.y;
                acc[k].z += qv.w * kv3.z;
                acc[k].w += qv.w * kv3.w;
            }
        }
#pragma unroll
        for (int k = 0; k < 5; k++) {
            int u = ublk * 5 + k;
            float4 sv = make_float4(acc[k].x * SCALE, acc[k].y * SCALE,
                                    acc[k].z * SCALE, acc[k].w * SCALE);
            *(float4*)(Ss + u * CHUNK + (jg << 2)) = sv;
        }
    }
    __syncwarp();

    {
        int w = t >> 5, lane = t & 31;
        for (int r = w * 5; r < w * 5 + 5; r++) {
            float v0 = Ss[r * CHUNK + lane];
            float v1 = Ss[r * CHUNK + lane + 32];
            float v2 = Ss[r * CHUNK + lane + 64];
            float v3 = Ss[r * CHUNK + lane + 96];
            float m = fmaxf(fmaxf(v0, v1), fmaxf(v2, v3));
#pragma unroll
            for (int o = 16; o; o >>= 1) m = fmaxf(m, __shfl_xor_sync(0xffffffffu, m, o));
            float e0 = __expf(v0 - m), e1 = __expf(v1 - m);
            float e2 = __expf(v2 - m), e3 = __expf(v3 - m);
            Ss[r * CHUNK + lane]      = e0;
            Ss[r * CHUNK + lane + 32] = e1;
            Ss[r * CHUNK + lane + 64] = e2;
            Ss[r * CHUNK + lane + 96] = e3;
            float s = e0 + e1 + e2 + e3;
#pragma unroll
            for (int o = 16; o; o >>= 1) s += __shfl_xor_sync(0xffffffffu, s, o);
            if (lane == 0) {
                g_pm[(bh * NSPLIT + split) * NT + r] = m;
                g_pl[(bh * NSPLIT + split) * NT + r] = s;
            }
        }
    }
    __syncthreads();

    for (int i = t; i < CHUNK * 16; i += 256) {
        int j = i >> 4, c = i & 15;
        ((float4*)KV)[i] =
            ((const float4*)V)[(((size_t)(b * LL + key0 + j) * HH + h) << 4) + c];
    }
    __syncthreads();

    {
        int ublk = t >> 5;
        int d4   = t & 15;
        int jh   = (t >> 4) & 1;
        float4 acc[5];
#pragma unroll
        for (int k = 0; k < 5; k++) acc[k] = make_float4(0.f, 0.f, 0.f, 0.f);
        const float4* Vs4 = (const float4*)KV;
        int j0 = jh * 64;
#pragma unroll 4
        for (int jj = 0; jj < 64; jj += 4) {
            int j = j0 + jj;
            float4 vv0 = Vs4[(j + 0) * 16 + d4];
            float4 vv1 = Vs4[(j + 1) * 16 + d4];
            float4 vv2 = Vs4[(j + 2) * 16 + d4];
            float4 vv3 = Vs4[(j + 3) * 16 + d4];
#pragma unroll
            for (int k = 0; k < 5; k++) {
                float4 p = *(const float4*)(Ss + (ublk * 5 + k) * CHUNK + j);
                acc[k].x += p.x * vv0.x;
                acc[k].y += p.x * vv0.y;
                acc[k].z += p.x * vv0.z;
                acc[k].w += p.x * vv0.w;
                acc[k].x += p.y * vv1.x;
                acc[k].y += p.y * vv1.y;
                acc[k].z += p.y * vv1.z;
                acc[k].w += p.y * vv1.w;
                acc[k].x += p.z * vv2.x;
                acc[k].y += p.z * vv2.y;
                acc[k].z += p.z * vv2.z;
                acc[k].w += p.z * vv2.w;
                acc[k].x += p.w * vv3.x;
                acc[k].y += p.w * vv3.y;
                acc[k].z += p.w * vv3.z;
                acc[k].w += p.w * vv3.w;
            }
        }
        __syncthreads();
#pragma unroll
        for (int k = 0; k < 5; k++) {
            int u = ublk * 5 + k;
            *(float4*)(Ss + (jh * NT + u) * 64 + (d4 << 2)) = acc[k];
        }
    }
    __syncthreads();

    {
        const float4* Ss4 = (const float4*)Ss;
        float4* po4 = (float4*)(g_po + (size_t)(bh * NSPLIT + split) * NT * DD);
        for (int i = t; i < NT * 16; i += 256) {
            float4 a = Ss4[i];
            float4 c = Ss4[NT * 16 + i];
            a.x += c.x; a.y += c.y; a.z += c.z; a.w += c.w;
            po4[i] = a;
        }
    }

    __syncthreads();
    __threadfence();
    if (t == 0)
        s_last = (atomicAdd(&g_cnt2[bh], 1) == NSPLIT - 1) ? 1 : 0;
    __syncthreads();
    if (!s_last) return;

    float* sw = smem;
    float* sl = smem + 640;
    if (t < NT) {
        float m = -3e38f;
#pragma unroll
        for (int s = 0; s < NSPLIT; s++)
            m = fmaxf(m, g_pm[(bh * NSPLIT + s) * NT + t]);
        float Ls = 0.f;
#pragma unroll
        for (int s = 0; s < NSPLIT; s++) {
            float w = __expf(g_pm[(bh * NSPLIT + s) * NT + t] - m);
            sw[t * NSPLIT + s] = w;
            Ls += g_pl[(bh * NSPLIT + s) * NT + t] * w;
        }
        sl[t] = Ls;
    }
    __syncthreads();
    for (int i = t; i < NT * DD; i += 256) {
        int u = i >> 6, d = i & 63;
        float acc = 0.f;
#pragma unroll
        for (int s = 0; s < NSPLIT; s++)
            acc += sw[u * NSPLIT + s] *
                   g_po[(size_t)(bh * NSPLIT + s) * NT * DD + i];
        out[(((size_t)(b * NT + u) * HH + h) << 6) + d] = acc / sl[u];
    }
    __syncthreads();
    if (t == 0) g_cnt2[bh] = 0;
}

// ---------------- launcher: 3 kernels ----------------
extern "C" void kernel_launch(void* const* d_in, const int* in_sizes, int n_in,
                              void* d_out, int out_size) {
    const float* Q   = (const float*)d_in[0];
    const float* K   = (const float*)d_in[1];
    const float* V   = (const float*)d_in[2];
    const void*  idx = d_in[3];

    prep_kernel<<<LL / 256, 256>>>(idx);

    size_t smemS = (size_t)(CK * DD + 1024) * sizeof(float);   // 102400 B
    cudaFuncSetAttribute(sample_m_kernel, cudaFuncAttributeMaxDynamicSharedMemorySize, (int)smemS);
    sample_m_kernel<<<BHN * LQ, 256, smemS>>>(Q, K);

    size_t smemD = (size_t)(NT * DD + 64 * KTPAD + NT * CHUNK) * sizeof(float); // 64512
    cudaFuncSetAttribute(attn_kernel, cudaFuncAttributeMaxDynamicSharedMemorySize, (int)smemD);
    attn_kernel<<<BHN * NSPLIT, 256, smemD>>>(Q, K, V, (float*)d_out);
}

// round 13
// speedup vs baseline: 3.0646x; 3.0646x over previous
#include <cuda_runtime.h>
#include <cstddef>

#define BB 4
#define LL 2048
#define HH 8
#define DD 64
#define SK 40
#define NT 40
#define BHN 32
#define NSPLIT 16
#define CHUNK 128
#define KTPAD 132
#define SCALE 0.125f

// ---------------- scratch ----------------
__device__ float g_M[BHN * LL];
__device__ int   g_top[BHN * NT];
__device__ float g_pm[BHN * NSPLIT * NT];
__device__ float g_pl[BHN * NSPLIT * NT];
__device__ float g_po[BHN * NSPLIT * NT * DD];
__device__ int   g_cnt1[BHN];   // zero-init; self-resetting
__device__ int   g_cnt2[BHN];   // zero-init; self-resetting

// ================= kernel 1: sample_m (R3 body, 1024-thread blocks for L1 reuse)
//                              + inline detect + fused topk =================
__global__ void __launch_bounds__(1024, 1)
sample_m_kernel(const float* __restrict__ Q,
                const float* __restrict__ K,
                const void*  __restrict__ idxbuf) {
    __shared__ float sM[LL];      // used only by the topk tail
    __shared__ int   s_last;

    int wid  = (blockIdx.x * blockDim.x + threadIdx.x) >> 5;   // global warp id (mapping unchanged)
    int lane = threadIdx.x & 31;
    int l  = wid % LL;
    int bh = wid / LL;
    int b = bh >> 3, h = bh & 7;
    int g  = lane >> 3;
    int li = lane & 7;

    // ---- inline dtype detection: read only the first 32 int64 slots (safe) ----
    {
        long long v = ((const long long*)idxbuf)[lane];
        int ok = (v >= 0 && v < LL);
        unsigned m = __ballot_sync(0xffffffffu, ok);
        int is64 = (m == 0xffffffffu);

        int ia, ib = 0;
        if (is64) {
            const long long* p = (const long long*)idxbuf + (long long)l * SK;
            ia = (int)p[lane];
            if (lane < SK - 32) ib = (int)p[32 + lane];
        } else {
            const int* p = (const int*)idxbuf + l * SK;
            ia = p[lane];
            if (lane < SK - 32) ib = p[32 + lane];
        }

        const float* qbase = Q + (((size_t)(b * LL + l) * HH + h) << 6) + (li << 3);
        const float4 qa = ((const float4*)qbase)[0];
        const float4 qb = ((const float4*)qbase)[1];

        const size_t kstride_h = ((size_t)h << 6) + ((size_t)li << 3);
        const float* Kb = K + ((size_t)b * LL * HH << 6);

        float mx = -3e38f, sm = 0.0f;
#pragma unroll
        for (int r = 0; r < 10; r++) {
            int s = 4 * r + g;
            int j = (s < 32) ? __shfl_sync(0xffffffffu, ia, s)
                             : __shfl_sync(0xffffffffu, ib, s - 32);
            const float4* kp = (const float4*)(Kb + (((size_t)j * HH) << 6) + kstride_h);
            float4 k0 = kp[0];
            float4 k1 = kp[1];
            float p = qa.x * k0.x;
            p = fmaf(qa.y, k0.y, p);
            p = fmaf(qa.z, k0.z, p);
            p = fmaf(qa.w, k0.w, p);
            p = fmaf(qb.x, k1.x, p);
            p = fmaf(qb.y, k1.y, p);
            p = fmaf(qb.z, k1.z, p);
            p = fmaf(qb.w, k1.w, p);
            p += __shfl_xor_sync(0xffffffffu, p, 1);
            p += __shfl_xor_sync(0xffffffffu, p, 2);
            p += __shfl_xor_sync(0xffffffffu, p, 4);
            mx = fmaxf(mx, p);
            sm += p;
        }
        mx = fmaxf(mx, __shfl_xor_sync(0xffffffffu, mx, 8));
        mx = fmaxf(mx, __shfl_xor_sync(0xffffffffu, mx, 16));
        sm += __shfl_xor_sync(0xffffffffu, sm, 8);
        sm += __shfl_xor_sync(0xffffffffu, sm, 16);
        if (lane == 0) g_M[bh * LL + l] = mx - sm * (1.0f / (float)LL);
    }

    // ---- fused topk: last block of this bh (LL/32 = 64 blocks per bh) ----
    __syncthreads();
    __threadfence();
    if (threadIdx.x == 0)
        s_last = (atomicAdd(&g_cnt1[bh], 1) == (LL / 32) - 1) ? 1 : 0;
    __syncthreads();
    if (!s_last) return;

    if (threadIdx.x < 32) {       // warp 0: proven topk-v3
        for (int i = lane; i < LL; i += 32) sM[i] = g_M[bh * LL + i];
        __syncwarp();

        int base = lane << 6;
        unsigned long long s0 = 0ull, s1 = 0ull, s2 = 0ull;
#pragma unroll 4
        for (int i = 0; i < 64; i++) {
            float x = sM[base + i];
            unsigned uv = __float_as_uint(x);
            uv ^= (uv >> 31) ? 0xffffffffu : 0x80000000u;
            unsigned long long k = ((unsigned long long)uv << 32)
                                 | (unsigned)(LL - 1 - (base + i));
            if (k > s0)      { s2 = s1; s1 = s0; s0 = k; }
            else if (k > s1) { s2 = s1; s1 = k; }
            else if (k > s2) { s2 = k; }
        }
        for (int it = 0; it < NT; it++) {
            unsigned ord0 = (unsigned)(s0 >> 32);
            unsigned m1 = __reduce_max_sync(0xffffffffu, ord0);
            unsigned lowp = (ord0 == m1) ? ((unsigned)s0 + 1u) : 0u;
            unsigned m2 = __reduce_max_sync(0xffffffffu, lowp);
            int wi = LL - (int)m2;
            if (lane == 0) g_top[bh * NT + it] = wi;
            if (lane == (wi >> 6)) {
                sM[wi] = -3e38f;
                s0 = s1; s1 = s2; s2 = 0ull;
                if (s0 == 0ull) {
                    for (int i = 0; i < 64; i++) {
                        float x = sM[base + i];
                        unsigned uv = __float_as_uint(x);
                        uv ^= (uv >> 31) ? 0xffffffffu : 0x80000000u;
                        unsigned long long k = ((unsigned long long)uv << 32)
                                             | (unsigned)(LL - 1 - (base + i));
                        if (k > s0)      { s2 = s1; s1 = s0; s0 = k; }
                        else if (k > s1) { s2 = s1; s1 = k; }
                        else if (k > s2) { s2 = k; }
                    }
                }
            }
            __syncwarp();
        }
        if (lane == 0) g_cnt1[bh] = 0;   // reset for next graph replay
    }
}

// ================= kernel 2: attn (R11-proven) + fused combine =================
__global__ void __launch_bounds__(256, 3)
attn_kernel(const float* __restrict__ Q,
            const float* __restrict__ K,
            const float* __restrict__ V,
            float* __restrict__ out) {
    extern __shared__ float smem[];
    __shared__ int s_last;
    int bh = blockIdx.x / NSPLIT, split = blockIdx.x % NSPLIT;
    int b = bh >> 3, h = bh & 7;
    int t = threadIdx.x;

    float* Qs = smem;                  // 2560
    float* KV = Qs + NT * DD;          // 8448
    float* Ss = KV + 64 * KTPAD;       // 5120

    for (int i = t; i < NT * 16; i += 256) {
        int u = i >> 4, c = i & 15;
        int ql = g_top[bh * NT + u];
        ((float4*)Qs)[i] =
            ((const float4*)Q)[(((size_t)(b * LL + ql) * HH + h) << 4) + c];
    }
    int key0 = split * CHUNK;
    for (int i = t; i < CHUNK * DD; i += 256) {
        int j = i >> 6, d = i & 63;
        KV[d * KTPAD + j] = K[(((size_t)(b * LL + key0 + j) * HH + h) << 6) + d];
    }
    __syncthreads();

    // ---- phase 1: scores ----
    {
        int ublk = t >> 5;
        int jg   = t & 31;
        float4 acc[5];
#pragma unroll
        for (int k = 0; k < 5; k++) acc[k] = make_float4(0.f, 0.f, 0.f, 0.f);
        const float4* Kt4 = (const float4*)KV;
#pragma unroll 4
        for (int d = 0; d < 64; d += 4) {
            float4 kv0 = Kt4[(d + 0) * 33 + jg];
            float4 kv1 = Kt4[(d + 1) * 33 + jg];
            float4 kv2 = Kt4[(d + 2) * 33 + jg];
            float4 kv3 = Kt4[(d + 3) * 33 + jg];
#pragma unroll
            for (int k = 0; k < 5; k++) {
                float4 qv = *(const float4*)(Qs + (ublk * 5 + k) * 64 + d);
                acc[k].x += qv.x * kv0.x;
                acc[k].y += qv.x * kv0.y;
                acc[k].z += qv.x * kv0.z;
                acc[k].w += qv.x * kv0.w;
                acc[k].x += qv.y * kv1.x;
                acc[k].y += qv.y * kv1.y;
                acc[k].z += qv.y * kv1.z;
                acc[k].w += qv.y * kv1.w;
                acc[k].x += qv.z * kv2.x;
                acc[k].y += qv.z * kv2.y;
                acc[k].z += qv.z * kv2.z;
                acc[k].w += qv.z * kv2.w;
                acc[k].x += qv.w * kv3.x;
                acc[k].y += qv.w * kv3.y;
                acc[k].z += qv.w * kv3.z;
                acc[k].w += qv.w * kv3.w;
            }
        }
#pragma unroll
        for (int k = 0; k < 5; k++) {
            int u = ublk * 5 + k;
            float4 sv = make_float4(acc[k].x * SCALE, acc[k].y * SCALE,
                                    acc[k].z * SCALE, acc[k].w * SCALE);
            *(float4*)(Ss + u * CHUNK + (jg << 2)) = sv;
        }
    }
    __syncwarp();

    // ---- phase 1.5: partial softmax ----
    {
        int w = t >> 5, lane = t & 31;
        for (int r = w * 5; r < w * 5 + 5; r++) {
            float v0 = Ss[r * CHUNK + lane];
            float v1 = Ss[r * CHUNK + lane + 32];
            float v2 = Ss[r * CHUNK + lane + 64];
            float v3 = Ss[r * CHUNK + lane + 96];
            float m = fmaxf(fmaxf(v0, v1), fmaxf(v2, v3));
#pragma unroll
            for (int o = 16; o; o >>= 1) m = fmaxf(m, __shfl_xor_sync(0xffffffffu, m, o));
            float e0 = __expf(v0 - m), e1 = __expf(v1 - m);
            float e2 = __expf(v2 - m), e3 = __expf(v3 - m);
            Ss[r * CHUNK + lane]      = e0;
            Ss[r * CHUNK + lane + 32] = e1;
            Ss[r * CHUNK + lane + 64] = e2;
            Ss[r * CHUNK + lane + 96] = e3;
            float s = e0 + e1 + e2 + e3;
#pragma unroll
            for (int o = 16; o; o >>= 1) s += __shfl_xor_sync(0xffffffffu, s, o);
            if (lane == 0) {
                g_pm[(bh * NSPLIT + split) * NT + r] = m;
                g_pl[(bh * NSPLIT + split) * NT + r] = s;
            }
        }
    }
    __syncthreads();

    // ---- deferred V staging ----
    for (int i = t; i < CHUNK * 16; i += 256) {
        int j = i >> 4, c = i & 15;
        ((float4*)KV)[i] =
            ((const float4*)V)[(((size_t)(b * LL + key0 + j) * HH + h) << 4) + c];
    }
    __syncthreads();

    // ---- phase 2: O_partial = P @ V ----
    {
        int ublk = t >> 5;
        int d4   = t & 15;
        int jh   = (t >> 4) & 1;
        float4 acc[5];
#pragma unroll
        for (int k = 0; k < 5; k++) acc[k] = make_float4(0.f, 0.f, 0.f, 0.f);
        const float4* Vs4 = (const float4*)KV;
        int j0 = jh * 64;
#pragma unroll 4
        for (int jj = 0; jj < 64; jj += 4) {
            int j = j0 + jj;
            float4 vv0 = Vs4[(j + 0) * 16 + d4];
            float4 vv1 = Vs4[(j + 1) * 16 + d4];
            float4 vv2 = Vs4[(j + 2) * 16 + d4];
            float4 vv3 = Vs4[(j + 3) * 16 + d4];
#pragma unroll
            for (int k = 0; k < 5; k++) {
                float4 p = *(const float4*)(Ss + (ublk * 5 + k) * CHUNK + j);
                acc[k].x += p.x * vv0.x;
                acc[k].y += p.x * vv0.y;
                acc[k].z += p.x * vv0.z;
                acc[k].w += p.x * vv0.w;
                acc[k].x += p.y * vv1.x;
                acc[k].y += p.y * vv1.y;
                acc[k].z += p.y * vv1.z;
                acc[k].w += p.y * vv1.w;
                acc[k].x += p.z * vv2.x;
                acc[k].y += p.z * vv2.y;
                acc[k].z += p.z * vv2.z;
                acc[k].w += p.z * vv2.w;
                acc[k].x += p.w * vv3.x;
                acc[k].y += p.w * vv3.y;
                acc[k].z += p.w * vv3.z;
                acc[k].w += p.w * vv3.w;
            }
        }
        __syncthreads();
#pragma unroll
        for (int k = 0; k < 5; k++) {
            int u = ublk * 5 + k;
            *(float4*)(Ss + (jh * NT + u) * 64 + (d4 << 2)) = acc[k];
        }
    }
    __syncthreads();

    {
        const float4* Ss4 = (const float4*)Ss;
        float4* po4 = (float4*)(g_po + (size_t)(bh * NSPLIT + split) * NT * DD);
        for (int i = t; i < NT * 16; i += 256) {
            float4 a = Ss4[i];
            float4 c = Ss4[NT * 16 + i];
            a.x += c.x; a.y += c.y; a.z += c.z; a.w += c.w;
            po4[i] = a;
        }
    }

    // ---- fused combine: last split-block of this bh ----
    __syncthreads();
    __threadfence();
    if (t == 0)
        s_last = (atomicAdd(&g_cnt2[bh], 1) == NSPLIT - 1) ? 1 : 0;
    __syncthreads();
    if (!s_last) return;

    float* sw = smem;            // Qs region, dead
    float* sl = smem + 640;
    if (t < NT) {
        float m = -3e38f;
#pragma unroll
        for (int s = 0; s < NSPLIT; s++)
            m = fmaxf(m, g_pm[(bh * NSPLIT + s) * NT + t]);
        float Ls = 0.f;
#pragma unroll
        for (int s = 0; s < NSPLIT; s++) {
            float w = __expf(g_pm[(bh * NSPLIT + s) * NT + t] - m);
            sw[t * NSPLIT + s] = w;
            Ls += g_pl[(bh * NSPLIT + s) * NT + t] * w;
        }
        sl[t] = Ls;
    }
    __syncthreads();
    for (int i = t; i < NT * DD; i += 256) {
        int u = i >> 6, d = i & 63;
        float acc = 0.f;
#pragma unroll
        for (int s = 0; s < NSPLIT; s++)
            acc += sw[u * NSPLIT + s] *
                   g_po[(size_t)(bh * NSPLIT + s) * NT * DD + i];
        out[(((size_t)(b * NT + u) * HH + h) << 6) + d] = acc / sl[u];
    }
    __syncthreads();
    if (t == 0) g_cnt2[bh] = 0;   // reset for next graph replay
}

// ---------------- launcher: 2 kernels ----------------
extern "C" void kernel_launch(void* const* d_in, const int* in_sizes, int n_in,
                              void* d_out, int out_size) {
    const float* Q   = (const float*)d_in[0];
    const float* K   = (const float*)d_in[1];
    const float* V   = (const float*)d_in[2];
    const void*  idx = d_in[3];

    sample_m_kernel<<<(BHN * LL) / 32, 1024>>>(Q, K, idx);

    size_t smemD = (size_t)(NT * DD + 64 * KTPAD + NT * CHUNK) * sizeof(float); // 64512
    cudaFuncSetAttribute(attn_kernel, cudaFuncAttributeMaxDynamicSharedMemorySize, (int)smemD);
    attn_kernel<<<BHN * NSPLIT, 256, smemD>>>(Q, K, V, (float*)d_out);
}

// round 14
// speedup vs baseline: 3.5660x; 1.1636x over previous
#include <cuda_runtime.h>
#include <cstddef>

#define BB 4
#define LL 2048
#define HH 8
#define DD 64
#define SK 40
#define NT 40
#define BHN 32
#define NSPLIT 16
#define CHUNK 128
#define KTPAD 132
#define SCALE 0.125f

// ---------------- scratch ----------------
__device__ float g_M[BHN * LL];
__device__ int   g_top[BHN * NT];
__device__ float g_pm[BHN * NSPLIT * NT];
__device__ float g_pl[BHN * NSPLIT * NT];
__device__ float g_po[BHN * NSPLIT * NT * DD];
__device__ int   g_cnt1[BHN];   // zero-init; self-resetting
__device__ int   g_cnt2[BHN];   // zero-init; self-resetting

// ---------------- packed f32x2 helpers ----------------
__device__ __forceinline__ unsigned long long pk2(float x, float y) {
    unsigned long long r;
    asm("mov.b64 %0, {%1, %2};" : "=l"(r) : "f"(x), "f"(y));
    return r;
}
__device__ __forceinline__ void upk2(unsigned long long v, float& x, float& y) {
    asm("mov.b64 {%0, %1}, %2;" : "=f"(x), "=f"(y) : "l"(v));
}
__device__ __forceinline__ unsigned long long ffma2(unsigned long long a,
                                                    unsigned long long b,
                                                    unsigned long long c) {
    unsigned long long d;
    asm("fma.rn.f32x2 %0, %1, %2, %3;" : "=l"(d) : "l"(a), "l"(b), "l"(c));
    return d;
}

// ================= kernel 1: sample_m (R11-proven) + inline detect + fused topk =================
__global__ void sample_m_kernel(const float* __restrict__ Q,
                                const float* __restrict__ K,
                                const void*  __restrict__ idxbuf) {
    __shared__ float sM[LL];
    __shared__ int   s_last;

    int wid  = (blockIdx.x * blockDim.x + threadIdx.x) >> 5;
    int lane = threadIdx.x & 31;
    int l  = wid % LL;
    int bh = wid / LL;
    int b = bh >> 3, h = bh & 7;
    int g  = lane >> 3;
    int li = lane & 7;

    {
        long long v = ((const long long*)idxbuf)[lane];
        int ok = (v >= 0 && v < LL);
        unsigned m = __ballot_sync(0xffffffffu, ok);
        int is64 = (m == 0xffffffffu);

        int ia, ib = 0;
        if (is64) {
            const long long* p = (const long long*)idxbuf + (long long)l * SK;
            ia = (int)p[lane];
            if (lane < SK - 32) ib = (int)p[32 + lane];
        } else {
            const int* p = (const int*)idxbuf + l * SK;
            ia = p[lane];
            if (lane < SK - 32) ib = p[32 + lane];
        }

        const float* qbase = Q + (((size_t)(b * LL + l) * HH + h) << 6) + (li << 3);
        const float4 qa = ((const float4*)qbase)[0];
        const float4 qb = ((const float4*)qbase)[1];

        const size_t kstride_h = ((size_t)h << 6) + ((size_t)li << 3);
        const float* Kb = K + ((size_t)b * LL * HH << 6);

        float mx = -3e38f, sm = 0.0f;
#pragma unroll
        for (int r = 0; r < 10; r++) {
            int s = 4 * r + g;
            int j = (s < 32) ? __shfl_sync(0xffffffffu, ia, s)
                             : __shfl_sync(0xffffffffu, ib, s - 32);
            const float4* kp = (const float4*)(Kb + (((size_t)j * HH) << 6) + kstride_h);
            float4 k0 = kp[0];
            float4 k1 = kp[1];
            float p = qa.x * k0.x;
            p = fmaf(qa.y, k0.y, p);
            p = fmaf(qa.z, k0.z, p);
            p = fmaf(qa.w, k0.w, p);
            p = fmaf(qb.x, k1.x, p);
            p = fmaf(qb.y, k1.y, p);
            p = fmaf(qb.z, k1.z, p);
            p = fmaf(qb.w, k1.w, p);
            p += __shfl_xor_sync(0xffffffffu, p, 1);
            p += __shfl_xor_sync(0xffffffffu, p, 2);
            p += __shfl_xor_sync(0xffffffffu, p, 4);
            mx = fmaxf(mx, p);
            sm += p;
        }
        mx = fmaxf(mx, __shfl_xor_sync(0xffffffffu, mx, 8));
        mx = fmaxf(mx, __shfl_xor_sync(0xffffffffu, mx, 16));
        sm += __shfl_xor_sync(0xffffffffu, sm, 8);
        sm += __shfl_xor_sync(0xffffffffu, sm, 16);
        if (lane == 0) g_M[bh * LL + l] = mx - sm * (1.0f / (float)LL);
    }

    __syncthreads();
    __threadfence();
    if (threadIdx.x == 0)
        s_last = (atomicAdd(&g_cnt1[bh], 1) == 255) ? 1 : 0;
    __syncthreads();
    if (!s_last) return;

    if (threadIdx.x < 32) {
        for (int i = lane; i < LL; i += 32) sM[i] = g_M[bh * LL + i];
        __syncwarp();

        int base = lane << 6;
        unsigned long long s0 = 0ull, s1 = 0ull, s2 = 0ull;
#pragma unroll 4
        for (int i = 0; i < 64; i++) {
            float x = sM[base + i];
            unsigned uv = __float_as_uint(x);
            uv ^= (uv >> 31) ? 0xffffffffu : 0x80000000u;
            unsigned long long k = ((unsigned long long)uv << 32)
                                 | (unsigned)(LL - 1 - (base + i));
            if (k > s0)      { s2 = s1; s1 = s0; s0 = k; }
            else if (k > s1) { s2 = s1; s1 = k; }
            else if (k > s2) { s2 = k; }
        }
        for (int it = 0; it < NT; it++) {
            unsigned ord0 = (unsigned)(s0 >> 32);
            unsigned m1 = __reduce_max_sync(0xffffffffu, ord0);
            unsigned lowp = (ord0 == m1) ? ((unsigned)s0 + 1u) : 0u;
            unsigned m2 = __reduce_max_sync(0xffffffffu, lowp);
            int wi = LL - (int)m2;
            if (lane == 0) g_top[bh * NT + it] = wi;
            if (lane == (wi >> 6)) {
                sM[wi] = -3e38f;
                s0 = s1; s1 = s2; s2 = 0ull;
                if (s0 == 0ull) {
                    for (int i = 0; i < 64; i++) {
                        float x = sM[base + i];
                        unsigned uv = __float_as_uint(x);
                        uv ^= (uv >> 31) ? 0xffffffffu : 0x80000000u;
                        unsigned long long k = ((unsigned long long)uv << 32)
                                             | (unsigned)(LL - 1 - (base + i));
                        if (k > s0)      { s2 = s1; s1 = s0; s0 = k; }
                        else if (k > s1) { s2 = s1; s1 = k; }
                        else if (k > s2) { s2 = k; }
                    }
                }
            }
            __syncwarp();
        }
        if (lane == 0) g_cnt1[bh] = 0;
    }
}

// ================= kernel 2: attn v8 (FFMA2, bit-identical order) + fused combine =================
__global__ void __launch_bounds__(256, 3)
attn_kernel(const float* __restrict__ Q,
            const float* __restrict__ K,
            const float* __restrict__ V,
            float* __restrict__ out) {
    extern __shared__ float smem[];
    __shared__ int s_last;
    int bh = blockIdx.x / NSPLIT, split = blockIdx.x % NSPLIT;
    int b = bh >> 3, h = bh & 7;
    int t = threadIdx.x;

    float* Qs = smem;                  // 2560
    float* KV = Qs + NT * DD;          // 8448: Kt (64x132) ph1, V (128x64) ph2
    float* Ss = KV + 64 * KTPAD;       // 5120

    for (int i = t; i < NT * 16; i += 256) {
        int u = i >> 4, c = i & 15;
        int ql = g_top[bh * NT + u];
        ((float4*)Qs)[i] =
            ((const float4*)Q)[(((size_t)(b * LL + ql) * HH + h) << 4) + c];
    }
    int key0 = split * CHUNK;
    for (int i = t; i < CHUNK * DD; i += 256) {
        int j = i >> 6, d = i & 63;
        KV[d * KTPAD + j] = K[(((size_t)(b * LL + key0 + j) * HH + h) << 6) + d];
    }
    __syncthreads();

    // ---- phase 1: scores via FFMA2; per S[u][j] accumulation d=0..63 sequential ----
    {
        int ublk = t >> 5;
        int jg   = t & 31;
        unsigned long long acc[5][2];
#pragma unroll
        for (int k = 0; k < 5; k++) { acc[k][0] = 0ull; acc[k][1] = 0ull; }
        const ulonglong2* Kt2 = (const ulonglong2*)KV;   // row = 33 ulonglong2
        const float4* Qs4 = (const float4*)Qs;
#pragma unroll 4
        for (int c = 0; c < 16; c++) {
            ulonglong2 kk0 = Kt2[(4 * c + 0) * 33 + jg];
            ulonglong2 kk1 = Kt2[(4 * c + 1) * 33 + jg];
            ulonglong2 kk2 = Kt2[(4 * c + 2) * 33 + jg];
            ulonglong2 kk3 = Kt2[(4 * c + 3) * 33 + jg];
#pragma unroll
            for (int k = 0; k < 5; k++) {
                float4 q = Qs4[(ublk * 5 + k) * 16 + c];
                unsigned long long qx = pk2(q.x, q.x);
                unsigned long long qy = pk2(q.y, q.y);
                unsigned long long qz = pk2(q.z, q.z);
                unsigned long long qw = pk2(q.w, q.w);
                acc[k][0] = ffma2(qx, kk0.x, acc[k][0]);
                acc[k][1] = ffma2(qx, kk0.y, acc[k][1]);
                acc[k][0] = ffma2(qy, kk1.x, acc[k][0]);
                acc[k][1] = ffma2(qy, kk1.y, acc[k][1]);
                acc[k][0] = ffma2(qz, kk2.x, acc[k][0]);
                acc[k][1] = ffma2(qz, kk2.y, acc[k][1]);
                acc[k][0] = ffma2(qw, kk3.x, acc[k][0]);
                acc[k][1] = ffma2(qw, kk3.y, acc[k][1]);
            }
        }
#pragma unroll
        for (int k = 0; k < 5; k++) {
            int u = ublk * 5 + k;
            float4 sv;
            upk2(acc[k][0], sv.x, sv.y);
            upk2(acc[k][1], sv.z, sv.w);
            sv.x *= SCALE; sv.y *= SCALE; sv.z *= SCALE; sv.w *= SCALE;
            *(float4*)(Ss + u * CHUNK + (jg << 2)) = sv;
        }
    }
    __syncwarp();

    // ---- phase 1.5: partial softmax (warp-local rows) ----
    {
        int w = t >> 5, lane = t & 31;
        for (int r = w * 5; r < w * 5 + 5; r++) {
            float v0 = Ss[r * CHUNK + lane];
            float v1 = Ss[r * CHUNK + lane + 32];
            float v2 = Ss[r * CHUNK + lane + 64];
            float v3 = Ss[r * CHUNK + lane + 96];
            float m = fmaxf(fmaxf(v0, v1), fmaxf(v2, v3));
#pragma unroll
            for (int o = 16; o; o >>= 1) m = fmaxf(m, __shfl_xor_sync(0xffffffffu, m, o));
            float e0 = __expf(v0 - m), e1 = __expf(v1 - m);
            float e2 = __expf(v2 - m), e3 = __expf(v3 - m);
            Ss[r * CHUNK + lane]      = e0;
            Ss[r * CHUNK + lane + 32] = e1;
            Ss[r * CHUNK + lane + 64] = e2;
            Ss[r * CHUNK + lane + 96] = e3;
            float s = e0 + e1 + e2 + e3;
#pragma unroll
            for (int o = 16; o; o >>= 1) s += __shfl_xor_sync(0xffffffffu, s, o);
            if (lane == 0) {
                g_pm[(bh * NSPLIT + split) * NT + r] = m;
                g_pl[(bh * NSPLIT + split) * NT + r] = s;
            }
        }
    }
    __syncthreads();

    // ---- deferred V staging ----
    for (int i = t; i < CHUNK * 16; i += 256) {
        int j = i >> 4, c = i & 15;
        ((float4*)KV)[i] =
            ((const float4*)V)[(((size_t)(b * LL + key0 + j) * HH + h) << 4) + c];
    }
    __syncthreads();

    // ---- phase 2: O = P @ V via FFMA2; per O[u][d] accumulation j sequential ----
    {
        int ublk = t >> 5;
        int d4   = t & 15;
        int jh   = (t >> 4) & 1;
        unsigned long long acc[5][2];
#pragma unroll
        for (int k = 0; k < 5; k++) { acc[k][0] = 0ull; acc[k][1] = 0ull; }
        const ulonglong2* Vs2 = (const ulonglong2*)KV;   // row = 16 ulonglong2
        int j0 = jh * 64;
#pragma unroll 4
        for (int jj = 0; jj < 64; jj += 4) {
            int j = j0 + jj;
            ulonglong2 vv0 = Vs2[(j + 0) * 16 + d4];
            ulonglong2 vv1 = Vs2[(j + 1) * 16 + d4];
            ulonglong2 vv2 = Vs2[(j + 2) * 16 + d4];
            ulonglong2 vv3 = Vs2[(j + 3) * 16 + d4];
#pragma unroll
            for (int k = 0; k < 5; k++) {
                float4 p = *(const float4*)(Ss + (ublk * 5 + k) * CHUNK + j);
                unsigned long long p0 = pk2(p.x, p.x);
                unsigned long long p1 = pk2(p.y, p.y);
                unsigned long long p2 = pk2(p.z, p.z);
                unsigned long long p3 = pk2(p.w, p.w);
                acc[k][0] = ffma2(p0, vv0.x, acc[k][0]);
                acc[k][1] = ffma2(p0, vv0.y, acc[k][1]);
                acc[k][0] = ffma2(p1, vv1.x, acc[k][0]);
                acc[k][1] = ffma2(p1, vv1.y, acc[k][1]);
                acc[k][0] = ffma2(p2, vv2.x, acc[k][0]);
                acc[k][1] = ffma2(p2, vv2.y, acc[k][1]);
                acc[k][0] = ffma2(p3, vv3.x, acc[k][0]);
                acc[k][1] = ffma2(p3, vv3.y, acc[k][1]);
            }
        }
        __syncthreads();   // all Ss (P) reads done before overwrite
#pragma unroll
        for (int k = 0; k < 5; k++) {
            int u = ublk * 5 + k;
            ulonglong2 ov;
            ov.x = acc[k][0];
            ov.y = acc[k][1];
            *(ulonglong2*)(Ss + (jh * NT + u) * 64 + (d4 << 2)) = ov;
        }
    }
    __syncthreads();

    {
        const float4* Ss4 = (const float4*)Ss;
        float4* po4 = (float4*)(g_po + (size_t)(bh * NSPLIT + split) * NT * DD);
        for (int i = t; i < NT * 16; i += 256) {
            float4 a = Ss4[i];
            float4 c = Ss4[NT * 16 + i];
            a.x += c.x; a.y += c.y; a.z += c.z; a.w += c.w;
            po4[i] = a;
        }
    }

    // ---- fused combine: last split-block of this bh ----
    __syncthreads();
    __threadfence();
    if (t == 0)
        s_last = (atomicAdd(&g_cnt2[bh], 1) == NSPLIT - 1) ? 1 : 0;
    __syncthreads();
    if (!s_last) return;

    float* sw = smem;
    float* sl = smem + 640;
    if (t < NT) {
        float m = -3e38f;
#pragma unroll
        for (int s = 0; s < NSPLIT; s++)
            m = fmaxf(m, g_pm[(bh * NSPLIT + s) * NT + t]);
        float Ls = 0.f;
#pragma unroll
        for (int s = 0; s < NSPLIT; s++) {
            float w = __expf(g_pm[(bh * NSPLIT + s) * NT + t] - m);
            sw[t * NSPLIT + s] = w;
            Ls += g_pl[(bh * NSPLIT + s) * NT + t] * w;
        }
        sl[t] = Ls;
    }
    __syncthreads();
    for (int i = t; i < NT * DD; i += 256) {
        int u = i >> 6, d = i & 63;
        float acc = 0.f;
#pragma unroll
        for (int s = 0; s < NSPLIT; s++)
            acc += sw[u * NSPLIT + s] *
                   g_po[(size_t)(bh * NSPLIT + s) * NT * DD + i];
        out[(((size_t)(b * NT + u) * HH + h) << 6) + d] = acc / sl[u];
    }
    __syncthreads();
    if (t == 0) g_cnt2[bh] = 0;
}

// ---------------- launcher: 2 kernels ----------------
extern "C" void kernel_launch(void* const* d_in, const int* in_sizes, int n_in,
                              void* d_out, int out_size) {
    const float* Q   = (const float*)d_in[0];
    const float* K   = (const float*)d_in[1];
    const float* V   = (const float*)d_in[2];
    const void*  idx = d_in[3];

    sample_m_kernel<<<(BHN * LL) / 8, 256>>>(Q, K, idx);

    size_t smemD = (size_t)(NT * DD + 64 * KTPAD + NT * CHUNK) * sizeof(float); // 64512
    cudaFuncSetAttribute(attn_kernel, cudaFuncAttributeMaxDynamicSharedMemorySize, (int)smemD);
    attn_kernel<<<BHN * NSPLIT, 256, smemD>>>(Q, K, V, (float*)d_out);
}

// round 15
// speedup vs baseline: 3.7572x; 1.0536x over previous
#include <cuda_runtime.h>
#include <cstddef>

#define BB 4
#define LL 2048
#define HH 8
#define DD 64
#define SK 40
#define NT 40
#define BHN 32
#define NSPLIT 16
#define CHUNK 128
#define KTPAD 132
#define SCALE 0.125f

#define NSAMPBLK (BHN * LL / 8)   // 8192 sample blocks
#define NATTNBLK (BHN * NSPLIT)   // 512 attn blocks

// ---------------- scratch ----------------
__device__ float g_M[BHN * LL];
__device__ int   g_top[BHN * NT];
__device__ float g_pm[BHN * NSPLIT * NT];
__device__ float g_pl[BHN * NSPLIT * NT];
__device__ float g_po[BHN * NSPLIT * NT * DD];
__device__ int   g_cnt1[BHN];     // zero-init; self-resetting
__device__ int   g_cnt2[BHN];     // zero-init; self-resetting
__device__ int   g_topdone[BHN];  // zero-init; self-resetting

// ---------------- packed f32x2 helpers ----------------
__device__ __forceinline__ unsigned long long pk2(float x, float y) {
    unsigned long long r;
    asm("mov.b64 %0, {%1, %2};" : "=l"(r) : "f"(x), "f"(y));
    return r;
}
__device__ __forceinline__ void upk2(unsigned long long v, float& x, float& y) {
    asm("mov.b64 {%0, %1}, %2;" : "=f"(x), "=f"(y) : "l"(v));
}
__device__ __forceinline__ unsigned long long ffma2(unsigned long long a,
                                                    unsigned long long b,
                                                    unsigned long long c) {
    unsigned long long d;
    asm("fma.rn.f32x2 %0, %1, %2, %3;" : "=l"(d) : "l"(a), "l"(b), "l"(c));
    return d;
}

// ================= fused kernel: sample_m(+topk) blocks, then attn(+combine) blocks =================
__global__ void __launch_bounds__(256, 3)
fused_kernel(const float* __restrict__ Q,
             const float* __restrict__ K,
             const float* __restrict__ V,
             const void*  __restrict__ idxbuf,
             float* __restrict__ out) {
    extern __shared__ float smem[];
    __shared__ int s_last;

    if (blockIdx.x < NSAMPBLK) {
        // ======================= SAMPLE ROLE (R11/R14-proven body) =======================
        int wid  = (blockIdx.x * blockDim.x + threadIdx.x) >> 5;
        int lane = threadIdx.x & 31;
        int l  = wid % LL;
        int bh = wid / LL;
        int b = bh >> 3, h = bh & 7;
        int g  = lane >> 3;
        int li = lane & 7;

        {
            long long v = ((const long long*)idxbuf)[lane];
            int ok = (v >= 0 && v < LL);
            unsigned m = __ballot_sync(0xffffffffu, ok);
            int is64 = (m == 0xffffffffu);

            int ia, ib = 0;
            if (is64) {
                const long long* p = (const long long*)idxbuf + (long long)l * SK;
                ia = (int)p[lane];
                if (lane < SK - 32) ib = (int)p[32 + lane];
            } else {
                const int* p = (const int*)idxbuf + l * SK;
                ia = p[lane];
                if (lane < SK - 32) ib = p[32 + lane];
            }

            const float* qbase = Q + (((size_t)(b * LL + l) * HH + h) << 6) + (li << 3);
            const float4 qa = ((const float4*)qbase)[0];
            const float4 qb = ((const float4*)qbase)[1];

            const size_t kstride_h = ((size_t)h << 6) + ((size_t)li << 3);
            const float* Kb = K + ((size_t)b * LL * HH << 6);

            float mx = -3e38f, sm = 0.0f;
#pragma unroll
            for (int r = 0; r < 10; r++) {
                int s = 4 * r + g;
                int j = (s < 32) ? __shfl_sync(0xffffffffu, ia, s)
                                 : __shfl_sync(0xffffffffu, ib, s - 32);
                const float4* kp = (const float4*)(Kb + (((size_t)j * HH) << 6) + kstride_h);
                float4 k0 = kp[0];
                float4 k1 = kp[1];
                float p = qa.x * k0.x;
                p = fmaf(qa.y, k0.y, p);
                p = fmaf(qa.z, k0.z, p);
                p = fmaf(qa.w, k0.w, p);
                p = fmaf(qb.x, k1.x, p);
                p = fmaf(qb.y, k1.y, p);
                p = fmaf(qb.z, k1.z, p);
                p = fmaf(qb.w, k1.w, p);
                p += __shfl_xor_sync(0xffffffffu, p, 1);
                p += __shfl_xor_sync(0xffffffffu, p, 2);
                p += __shfl_xor_sync(0xffffffffu, p, 4);
                mx = fmaxf(mx, p);
                sm += p;
            }
            mx = fmaxf(mx, __shfl_xor_sync(0xffffffffu, mx, 8));
            mx = fmaxf(mx, __shfl_xor_sync(0xffffffffu, mx, 16));
            sm += __shfl_xor_sync(0xffffffffu, sm, 8);
            sm += __shfl_xor_sync(0xffffffffu, sm, 16);
            if (lane == 0) g_M[bh * LL + l] = mx - sm * (1.0f / (float)LL);
        }

        __syncthreads();
        __threadfence();
        if (threadIdx.x == 0)
            s_last = (atomicAdd(&g_cnt1[bh], 1) == 255) ? 1 : 0;
        __syncthreads();
        if (!s_last) return;

        if (threadIdx.x < 32) {
            float* sM = smem;   // dynamic smem, 2048 floats
            for (int i = lane; i < LL; i += 32) sM[i] = g_M[bh * LL + i];
            __syncwarp();

            int base = lane << 6;
            unsigned long long s0 = 0ull, s1 = 0ull, s2 = 0ull;
#pragma unroll 4
            for (int i = 0; i < 64; i++) {
                float x = sM[base + i];
                unsigned uv = __float_as_uint(x);
                uv ^= (uv >> 31) ? 0xffffffffu : 0x80000000u;
                unsigned long long k = ((unsigned long long)uv << 32)
                                     | (unsigned)(LL - 1 - (base + i));
                if (k > s0)      { s2 = s1; s1 = s0; s0 = k; }
                else if (k > s1) { s2 = s1; s1 = k; }
                else if (k > s2) { s2 = k; }
            }
            for (int it = 0; it < NT; it++) {
                unsigned ord0 = (unsigned)(s0 >> 32);
                unsigned m1 = __reduce_max_sync(0xffffffffu, ord0);
                unsigned lowp = (ord0 == m1) ? ((unsigned)s0 + 1u) : 0u;
                unsigned m2 = __reduce_max_sync(0xffffffffu, lowp);
                int wi = LL - (int)m2;
                if (lane == 0) g_top[bh * NT + it] = wi;
                if (lane == (wi >> 6)) {
                    sM[wi] = -3e38f;
                    s0 = s1; s1 = s2; s2 = 0ull;
                    if (s0 == 0ull) {
                        for (int i = 0; i < 64; i++) {
                            float x = sM[base + i];
                            unsigned uv = __float_as_uint(x);
                            uv ^= (uv >> 31) ? 0xffffffffu : 0x80000000u;
                            unsigned long long k = ((unsigned long long)uv << 32)
                                                 | (unsigned)(LL - 1 - (base + i));
                            if (k > s0)      { s2 = s1; s1 = s0; s0 = k; }
                            else if (k > s1) { s2 = s1; s1 = k; }
                            else if (k > s2) { s2 = k; }
                        }
                    }
                }
                __syncwarp();
            }
            if (lane == 0) {
                g_cnt1[bh] = 0;
                __threadfence();
                atomicExch(&g_topdone[bh], 1);   // release
            }
        }
        return;
    }

    // ======================= ATTN ROLE (R14-proven body) =======================
    int bid2 = blockIdx.x - NSAMPBLK;
    int bh = bid2 / NSPLIT, split = bid2 % NSPLIT;
    int b = bh >> 3, h = bh & 7;
    int t = threadIdx.x;

    float* Qs = smem;                  // 2560
    float* KV = Qs + NT * DD;          // 8448
    float* Ss = KV + 64 * KTPAD;       // 5120

    // K staging first — independent of g_top, overlaps the spin
    int key0 = split * CHUNK;
    for (int i = t; i < CHUNK * DD; i += 256) {
        int j = i >> 6, d = i & 63;
        KV[d * KTPAD + j] = K[(((size_t)(b * LL + key0 + j) * HH + h) << 6) + d];
    }

    // spin until topk for this bh is published
    if (t == 0) {
        while (*(volatile int*)&g_topdone[bh] == 0) { }
        s_last = 0;   // reuse as dummy write to order
    }
    __syncthreads();
    __threadfence();

    for (int i = t; i < NT * 16; i += 256) {
        int u = i >> 4, c = i & 15;
        int ql = g_top[bh * NT + u];
        ((float4*)Qs)[i] =
            ((const float4*)Q)[(((size_t)(b * LL + ql) * HH + h) << 4) + c];
    }
    __syncthreads();

    // ---- phase 1: scores via FFMA2 ----
    {
        int ublk = t >> 5;
        int jg   = t & 31;
        unsigned long long acc[5][2];
#pragma unroll
        for (int k = 0; k < 5; k++) { acc[k][0] = 0ull; acc[k][1] = 0ull; }
        const ulonglong2* Kt2 = (const ulonglong2*)KV;
        const float4* Qs4 = (const float4*)Qs;
#pragma unroll 4
        for (int c = 0; c < 16; c++) {
            ulonglong2 kk0 = Kt2[(4 * c + 0) * 33 + jg];
            ulonglong2 kk1 = Kt2[(4 * c + 1) * 33 + jg];
            ulonglong2 kk2 = Kt2[(4 * c + 2) * 33 + jg];
            ulonglong2 kk3 = Kt2[(4 * c + 3) * 33 + jg];
#pragma unroll
            for (int k = 0; k < 5; k++) {
                float4 q = Qs4[(ublk * 5 + k) * 16 + c];
                unsigned long long qx = pk2(q.x, q.x);
                unsigned long long qy = pk2(q.y, q.y);
                unsigned long long qz = pk2(q.z, q.z);
                unsigned long long qw = pk2(q.w, q.w);
                acc[k][0] = ffma2(qx, kk0.x, acc[k][0]);
                acc[k][1] = ffma2(qx, kk0.y, acc[k][1]);
                acc[k][0] = ffma2(qy, kk1.x, acc[k][0]);
                acc[k][1] = ffma2(qy, kk1.y, acc[k][1]);
                acc[k][0] = ffma2(qz, kk2.x, acc[k][0]);
                acc[k][1] = ffma2(qz, kk2.y, acc[k][1]);
                acc[k][0] = ffma2(qw, kk3.x, acc[k][0]);
                acc[k][1] = ffma2(qw, kk3.y, acc[k][1]);
            }
        }
#pragma unroll
        for (int k = 0; k < 5; k++) {
            int u = ublk * 5 + k;
            float4 sv;
            upk2(acc[k][0], sv.x, sv.y);
            upk2(acc[k][1], sv.z, sv.w);
            sv.x *= SCALE; sv.y *= SCALE; sv.z *= SCALE; sv.w *= SCALE;
            *(float4*)(Ss + u * CHUNK + (jg << 2)) = sv;
        }
    }
    __syncwarp();

    // ---- phase 1.5: partial softmax ----
    {
        int w = t >> 5, lane = t & 31;
        for (int r = w * 5; r < w * 5 + 5; r++) {
            float v0 = Ss[r * CHUNK + lane];
            float v1 = Ss[r * CHUNK + lane + 32];
            float v2 = Ss[r * CHUNK + lane + 64];
            float v3 = Ss[r * CHUNK + lane + 96];
            float m = fmaxf(fmaxf(v0, v1), fmaxf(v2, v3));
#pragma unroll
            for (int o = 16; o; o >>= 1) m = fmaxf(m, __shfl_xor_sync(0xffffffffu, m, o));
            float e0 = __expf(v0 - m), e1 = __expf(v1 - m);
            float e2 = __expf(v2 - m), e3 = __expf(v3 - m);
            Ss[r * CHUNK + lane]      = e0;
            Ss[r * CHUNK + lane + 32] = e1;
            Ss[r * CHUNK + lane + 64] = e2;
            Ss[r * CHUNK + lane + 96] = e3;
            float s = e0 + e1 + e2 + e3;
#pragma unroll
            for (int o = 16; o; o >>= 1) s += __shfl_xor_sync(0xffffffffu, s, o);
            if (lane == 0) {
                g_pm[(bh * NSPLIT + split) * NT + r] = m;
                g_pl[(bh * NSPLIT + split) * NT + r] = s;
            }
        }
    }
    __syncthreads();

    // ---- deferred V staging ----
    for (int i = t; i < CHUNK * 16; i += 256) {
        int j = i >> 4, c = i & 15;
        ((float4*)KV)[i] =
            ((const float4*)V)[(((size_t)(b * LL + key0 + j) * HH + h) << 4) + c];
    }
    __syncthreads();

    // ---- phase 2: O = P @ V via FFMA2 ----
    {
        int ublk = t >> 5;
        int d4   = t & 15;
        int jh   = (t >> 4) & 1;
        unsigned long long acc[5][2];
#pragma unroll
        for (int k = 0; k < 5; k++) { acc[k][0] = 0ull; acc[k][1] = 0ull; }
        const ulonglong2* Vs2 = (const ulonglong2*)KV;
        int j0 = jh * 64;
#pragma unroll 4
        for (int jj = 0; jj < 64; jj += 4) {
            int j = j0 + jj;
            ulonglong2 vv0 = Vs2[(j + 0) * 16 + d4];
            ulonglong2 vv1 = Vs2[(j + 1) * 16 + d4];
            ulonglong2 vv2 = Vs2[(j + 2) * 16 + d4];
            ulonglong2 vv3 = Vs2[(j + 3) * 16 + d4];
#pragma unroll
            for (int k = 0; k < 5; k++) {
                float4 p = *(const float4*)(Ss + (ublk * 5 + k) * CHUNK + j);
                unsigned long long p0 = pk2(p.x, p.x);
                unsigned long long p1 = pk2(p.y, p.y);
                unsigned long long p2 = pk2(p.z, p.z);
                unsigned long long p3 = pk2(p.w, p.w);
                acc[k][0] = ffma2(p0, vv0.x, acc[k][0]);
                acc[k][1] = ffma2(p0, vv0.y, acc[k][1]);
                acc[k][0] = ffma2(p1, vv1.x, acc[k][0]);
                acc[k][1] = ffma2(p1, vv1.y, acc[k][1]);
                acc[k][0] = ffma2(p2, vv2.x, acc[k][0]);
                acc[k][1] = ffma2(p2, vv2.y, acc[k][1]);
                acc[k][0] = ffma2(p3, vv3.x, acc[k][0]);
                acc[k][1] = ffma2(p3, vv3.y, acc[k][1]);
            }
        }
        __syncthreads();
#pragma unroll
        for (int k = 0; k < 5; k++) {
            int u = ublk * 5 + k;
            ulonglong2 ov;
            ov.x = acc[k][0];
            ov.y = acc[k][1];
            *(ulonglong2*)(Ss + (jh * NT + u) * 64 + (d4 << 2)) = ov;
        }
    }
    __syncthreads();

    {
        const float4* Ss4 = (const float4*)Ss;
        float4* po4 = (float4*)(g_po + (size_t)(bh * NSPLIT + split) * NT * DD);
        for (int i = t; i < NT * 16; i += 256) {
            float4 a = Ss4[i];
            float4 c = Ss4[NT * 16 + i];
            a.x += c.x; a.y += c.y; a.z += c.z; a.w += c.w;
            po4[i] = a;
        }
    }

    // ---- fused combine: last split-block of this bh ----
    __syncthreads();
    __threadfence();
    if (t == 0)
        s_last = (atomicAdd(&g_cnt2[bh], 1) == NSPLIT - 1) ? 1 : 0;
    __syncthreads();
    if (!s_last) return;

    float* sw = smem;
    float* sl = smem + 640;
    if (t < NT) {
        float m = -3e38f;
#pragma unroll
        for (int s = 0; s < NSPLIT; s++)
            m = fmaxf(m, g_pm[(bh * NSPLIT + s) * NT + t]);
        float Ls = 0.f;
#pragma unroll
        for (int s = 0; s < NSPLIT; s++) {
            float w = __expf(g_pm[(bh * NSPLIT + s) * NT + t] - m);
            sw[t * NSPLIT + s] = w;
            Ls += g_pl[(bh * NSPLIT + s) * NT + t] * w;
        }
        sl[t] = Ls;
    }
    __syncthreads();
    for (int i = t; i < NT * DD; i += 256) {
        int u = i >> 6, d = i & 63;
        float acc = 0.f;
#pragma unroll
        for (int s = 0; s < NSPLIT; s++)
            acc += sw[u * NSPLIT + s] *
                   g_po[(size_t)(bh * NSPLIT + s) * NT * DD + i];
        out[(((size_t)(b * NT + u) * HH + h) << 6) + d] = acc / sl[u];
    }
    __syncthreads();
    if (t == 0) {
        g_cnt2[bh] = 0;
        g_topdone[bh] = 0;   // reset for next graph replay
    }
}

// ---------------- launcher: 1 kernel ----------------
extern "C" void kernel_launch(void* const* d_in, const int* in_sizes, int n_in,
                              void* d_out, int out_size) {
    const float* Q   = (const float*)d_in[0];
    const float* K   = (const float*)d_in[1];
    const float* V   = (const float*)d_in[2];
    const void*  idx = d_in[3];

    size_t smemD = (size_t)(NT * DD + 64 * KTPAD + NT * CHUNK) * sizeof(float); // 64512
    cudaFuncSetAttribute(fused_kernel, cudaFuncAttributeMaxDynamicSharedMemorySize, (int)smemD);
    fused_kernel<<<NSAMPBLK + NATTNBLK, 256, smemD>>>(Q, K, V, idx, (float*)d_out);
}

// round 16
// speedup vs baseline: 4.0164x; 1.0690x over previous
#include <cuda_runtime.h>
#include <cstddef>

#define BB 4
#define LL 2048
#define HH 8
#define DD 64
#define SK 40
#define NT 40
#define BHN 32
#define NSPLIT 16
#define CHUNK 128
#define KTPAD 132
#define SCALE 0.125f

#define NSAMPBLK (BHN * LL / 16)  // 4096 sample blocks (2 l's per warp)
#define NATTNBLK (BHN * NSPLIT)   // 512 attn blocks

// ---------------- scratch ----------------
__device__ float g_M[BHN * LL];
__device__ int   g_top[BHN * NT];
__device__ float g_pm[BHN * NSPLIT * NT];
__device__ float g_pl[BHN * NSPLIT * NT];
__device__ float g_po[BHN * NSPLIT * NT * DD];
__device__ int   g_cnt1[BHN];     // zero-init; self-resetting
__device__ int   g_cnt2[BHN];     // zero-init; self-resetting
__device__ int   g_topdone[BHN];  // zero-init; self-resetting

// ---------------- packed f32x2 helpers ----------------
__device__ __forceinline__ unsigned long long pk2(float x, float y) {
    unsigned long long r;
    asm("mov.b64 %0, {%1, %2};" : "=l"(r) : "f"(x), "f"(y));
    return r;
}
__device__ __forceinline__ void upk2(unsigned long long v, float& x, float& y) {
    asm("mov.b64 {%0, %1}, %2;" : "=f"(x), "=f"(y) : "l"(v));
}
__device__ __forceinline__ unsigned long long ffma2(unsigned long long a,
                                                    unsigned long long b,
                                                    unsigned long long c) {
    unsigned long long d;
    asm("fma.rn.f32x2 %0, %1, %2, %3;" : "=l"(d) : "l"(a), "l"(b), "l"(c));
    return d;
}

// ================= fused kernel =================
__global__ void __launch_bounds__(256, 3)
fused_kernel(const float* __restrict__ Q,
             const float* __restrict__ K,
             const float* __restrict__ V,
             const void*  __restrict__ idxbuf,
             float* __restrict__ out) {
    extern __shared__ float smem[];
    __shared__ int s_last;

    if (blockIdx.x < NSAMPBLK) {
        // ======================= SAMPLE ROLE: 2 l's per warp =======================
        int wid  = (blockIdx.x * blockDim.x + threadIdx.x) >> 5;   // 0 .. BHN*LL/2-1
        int lane = threadIdx.x & 31;
        int lp = wid % (LL / 2);
        int bh = wid / (LL / 2);
        int l0 = lp * 2, l1 = l0 + 1;
        int b = bh >> 3, h = bh & 7;
        int g  = lane >> 3;
        int li = lane & 7;

        {
            long long v = ((const long long*)idxbuf)[lane];
            int ok = (v >= 0 && v < LL);
            unsigned m = __ballot_sync(0xffffffffu, ok);
            int is64 = (m == 0xffffffffu);

            int ia0, ib0 = 0, ia1, ib1 = 0;
            if (is64) {
                const long long* p0 = (const long long*)idxbuf + (long long)l0 * SK;
                const long long* p1 = (const long long*)idxbuf + (long long)l1 * SK;
                ia0 = (int)p0[lane];
                ia1 = (int)p1[lane];
                if (lane < SK - 32) { ib0 = (int)p0[32 + lane]; ib1 = (int)p1[32 + lane]; }
            } else {
                const int* p0 = (const int*)idxbuf + l0 * SK;
                const int* p1 = (const int*)idxbuf + l1 * SK;
                ia0 = p0[lane];
                ia1 = p1[lane];
                if (lane < SK - 32) { ib0 = p0[32 + lane]; ib1 = p1[32 + lane]; }
            }

            const float* q0base = Q + (((size_t)(b * LL + l0) * HH + h) << 6) + (li << 3);
            const float* q1base = Q + (((size_t)(b * LL + l1) * HH + h) << 6) + (li << 3);
            const float4 qa0 = ((const float4*)q0base)[0];
            const float4 qb0 = ((const float4*)q0base)[1];
            const float4 qa1 = ((const float4*)q1base)[0];
            const float4 qb1 = ((const float4*)q1base)[1];

            const size_t kstride_h = ((size_t)h << 6) + ((size_t)li << 3);
            const float* Kb = K + ((size_t)b * LL * HH << 6);

            float mx0 = -3e38f, sm0 = 0.0f;
            float mx1 = -3e38f, sm1 = 0.0f;
#pragma unroll
            for (int r = 0; r < 10; r++) {
                int s = 4 * r + g;
                int j0 = (s < 32) ? __shfl_sync(0xffffffffu, ia0, s)
                                  : __shfl_sync(0xffffffffu, ib0, s - 32);
                int j1 = (s < 32) ? __shfl_sync(0xffffffffu, ia1, s)
                                  : __shfl_sync(0xffffffffu, ib1, s - 32);
                const float4* kp0 = (const float4*)(Kb + (((size_t)j0 * HH) << 6) + kstride_h);
                const float4* kp1 = (const float4*)(Kb + (((size_t)j1 * HH) << 6) + kstride_h);
                float4 k00 = kp0[0];
                float4 k01 = kp0[1];
                float4 k10 = kp1[0];
                float4 k11 = kp1[1];

                float p0 = qa0.x * k00.x;
                p0 = fmaf(qa0.y, k00.y, p0);
                p0 = fmaf(qa0.z, k00.z, p0);
                p0 = fmaf(qa0.w, k00.w, p0);
                p0 = fmaf(qb0.x, k01.x, p0);
                p0 = fmaf(qb0.y, k01.y, p0);
                p0 = fmaf(qb0.z, k01.z, p0);
                p0 = fmaf(qb0.w, k01.w, p0);

                float p1 = qa1.x * k10.x;
                p1 = fmaf(qa1.y, k10.y, p1);
                p1 = fmaf(qa1.z, k10.z, p1);
                p1 = fmaf(qa1.w, k10.w, p1);
                p1 = fmaf(qb1.x, k11.x, p1);
                p1 = fmaf(qb1.y, k11.y, p1);
                p1 = fmaf(qb1.z, k11.z, p1);
                p1 = fmaf(qb1.w, k11.w, p1);

                p0 += __shfl_xor_sync(0xffffffffu, p0, 1);
                p1 += __shfl_xor_sync(0xffffffffu, p1, 1);
                p0 += __shfl_xor_sync(0xffffffffu, p0, 2);
                p1 += __shfl_xor_sync(0xffffffffu, p1, 2);
                p0 += __shfl_xor_sync(0xffffffffu, p0, 4);
                p1 += __shfl_xor_sync(0xffffffffu, p1, 4);

                mx0 = fmaxf(mx0, p0);
                sm0 += p0;
                mx1 = fmaxf(mx1, p1);
                sm1 += p1;
            }
            mx0 = fmaxf(mx0, __shfl_xor_sync(0xffffffffu, mx0, 8));
            mx0 = fmaxf(mx0, __shfl_xor_sync(0xffffffffu, mx0, 16));
            sm0 += __shfl_xor_sync(0xffffffffu, sm0, 8);
            sm0 += __shfl_xor_sync(0xffffffffu, sm0, 16);
            mx1 = fmaxf(mx1, __shfl_xor_sync(0xffffffffu, mx1, 8));
            mx1 = fmaxf(mx1, __shfl_xor_sync(0xffffffffu, mx1, 16));
            sm1 += __shfl_xor_sync(0xffffffffu, sm1, 8);
            sm1 += __shfl_xor_sync(0xffffffffu, sm1, 16);
            if (lane == 0) {
                g_M[bh * LL + l0] = mx0 - sm0 * (1.0f / (float)LL);
                g_M[bh * LL + l1] = mx1 - sm1 * (1.0f / (float)LL);
            }
        }

        __syncthreads();
        __threadfence();
        if (threadIdx.x == 0)
            s_last = (atomicAdd(&g_cnt1[bh], 1) == 127) ? 1 : 0;   // 128 blocks per bh
        __syncthreads();
        if (!s_last) return;

        if (threadIdx.x < 32) {
            float* sM = smem;   // dynamic smem, 2048 floats
            for (int i = lane; i < LL; i += 32) sM[i] = g_M[bh * LL + i];
            __syncwarp();

            int base = lane << 6;
            unsigned long long s0 = 0ull, s1 = 0ull, s2 = 0ull;
#pragma unroll 4
            for (int i = 0; i < 64; i++) {
                float x = sM[base + i];
                unsigned uv = __float_as_uint(x);
                uv ^= (uv >> 31) ? 0xffffffffu : 0x80000000u;
                unsigned long long k = ((unsigned long long)uv << 32)
                                     | (unsigned)(LL - 1 - (base + i));
                if (k > s0)      { s2 = s1; s1 = s0; s0 = k; }
                else if (k > s1) { s2 = s1; s1 = k; }
                else if (k > s2) { s2 = k; }
            }
            for (int it = 0; it < NT; it++) {
                unsigned ord0 = (unsigned)(s0 >> 32);
                unsigned m1 = __reduce_max_sync(0xffffffffu, ord0);
                unsigned lowp = (ord0 == m1) ? ((unsigned)s0 + 1u) : 0u;
                unsigned m2 = __reduce_max_sync(0xffffffffu, lowp);
                int wi = LL - (int)m2;
                if (lane == 0) g_top[bh * NT + it] = wi;
                if (lane == (wi >> 6)) {
                    sM[wi] = -3e38f;
                    s0 = s1; s1 = s2; s2 = 0ull;
                    if (s0 == 0ull) {
                        for (int i = 0; i < 64; i++) {
                            float x = sM[base + i];
                            unsigned uv = __float_as_uint(x);
                            uv ^= (uv >> 31) ? 0xffffffffu : 0x80000000u;
                            unsigned long long k = ((unsigned long long)uv << 32)
                                                 | (unsigned)(LL - 1 - (base + i));
                            if (k > s0)      { s2 = s1; s1 = s0; s0 = k; }
                            else if (k > s1) { s2 = s1; s1 = k; }
                            else if (k > s2) { s2 = k; }
                        }
                    }
                }
                __syncwarp();
            }
            if (lane == 0) {
                g_cnt1[bh] = 0;
                __threadfence();
                atomicExch(&g_topdone[bh], 1);   // release
            }
        }
        return;
    }

    // ======================= ATTN ROLE (R15-proven) =======================
    int bid2 = blockIdx.x - NSAMPBLK;
    int bh = bid2 / NSPLIT, split = bid2 % NSPLIT;
    int b = bh >> 3, h = bh & 7;
    int t = threadIdx.x;

    float* Qs = smem;                  // 2560
    float* KV = Qs + NT * DD;          // 8448
    float* Ss = KV + 64 * KTPAD;       // 5120

    int key0 = split * CHUNK;
    for (int i = t; i < CHUNK * DD; i += 256) {
        int j = i >> 6, d = i & 63;
        KV[d * KTPAD + j] = K[(((size_t)(b * LL + key0 + j) * HH + h) << 6) + d];
    }

    if (t == 0) {
        while (*(volatile int*)&g_topdone[bh] == 0) { }
        s_last = 0;
    }
    __syncthreads();
    __threadfence();

    for (int i = t; i < NT * 16; i += 256) {
        int u = i >> 4, c = i & 15;
        int ql = g_top[bh * NT + u];
        ((float4*)Qs)[i] =
            ((const float4*)Q)[(((size_t)(b * LL + ql) * HH + h) << 4) + c];
    }
    __syncthreads();

    // ---- phase 1: scores via FFMA2 ----
    {
        int ublk = t >> 5;
        int jg   = t & 31;
        unsigned long long acc[5][2];
#pragma unroll
        for (int k = 0; k < 5; k++) { acc[k][0] = 0ull; acc[k][1] = 0ull; }
        const ulonglong2* Kt2 = (const ulonglong2*)KV;
        const float4* Qs4 = (const float4*)Qs;
#pragma unroll 4
        for (int c = 0; c < 16; c++) {
            ulonglong2 kk0 = Kt2[(4 * c + 0) * 33 + jg];
            ulonglong2 kk1 = Kt2[(4 * c + 1) * 33 + jg];
            ulonglong2 kk2 = Kt2[(4 * c + 2) * 33 + jg];
            ulonglong2 kk3 = Kt2[(4 * c + 3) * 33 + jg];
#pragma unroll
            for (int k = 0; k < 5; k++) {
                float4 q = Qs4[(ublk * 5 + k) * 16 + c];
                unsigned long long qx = pk2(q.x, q.x);
                unsigned long long qy = pk2(q.y, q.y);
                unsigned long long qz = pk2(q.z, q.z);
                unsigned long long qw = pk2(q.w, q.w);
                acc[k][0] = ffma2(qx, kk0.x, acc[k][0]);
                acc[k][1] = ffma2(qx, kk0.y, acc[k][1]);
                acc[k][0] = ffma2(qy, kk1.x, acc[k][0]);
                acc[k][1] = ffma2(qy, kk1.y, acc[k][1]);
                acc[k][0] = ffma2(qz, kk2.x, acc[k][0]);
                acc[k][1] = ffma2(qz, kk2.y, acc[k][1]);
                acc[k][0] = ffma2(qw, kk3.x, acc[k][0]);
                acc[k][1] = ffma2(qw, kk3.y, acc[k][1]);
            }
        }
#pragma unroll
        for (int k = 0; k < 5; k++) {
            int u = ublk * 5 + k;
            float4 sv;
            upk2(acc[k][0], sv.x, sv.y);
            upk2(acc[k][1], sv.z, sv.w);
            sv.x *= SCALE; sv.y *= SCALE; sv.z *= SCALE; sv.w *= SCALE;
            *(float4*)(Ss + u * CHUNK + (jg << 2)) = sv;
        }
    }
    __syncwarp();

    // ---- phase 1.5: partial softmax ----
    {
        int w = t >> 5, lane = t & 31;
        for (int r = w * 5; r < w * 5 + 5; r++) {
            float v0 = Ss[r * CHUNK + lane];
            float v1 = Ss[r * CHUNK + lane + 32];
            float v2 = Ss[r * CHUNK + lane + 64];
            float v3 = Ss[r * CHUNK + lane + 96];
            float m = fmaxf(fmaxf(v0, v1), fmaxf(v2, v3));
#pragma unroll
            for (int o = 16; o; o >>= 1) m = fmaxf(m, __shfl_xor_sync(0xffffffffu, m, o));
            float e0 = __expf(v0 - m), e1 = __expf(v1 - m);
            float e2 = __expf(v2 - m), e3 = __expf(v3 - m);
            Ss[r * CHUNK + lane]      = e0;
            Ss[r * CHUNK + lane + 32] = e1;
            Ss[r * CHUNK + lane + 64] = e2;
            Ss[r * CHUNK + lane + 96] = e3;
            float s = e0 + e1 + e2 + e3;
#pragma unroll
            for (int o = 16; o; o >>= 1) s += __shfl_xor_sync(0xffffffffu, s, o);
            if (lane == 0) {
                g_pm[(bh * NSPLIT + split) * NT + r] = m;
                g_pl[(bh * NSPLIT + split) * NT + r] = s;
            }
        }
    }
    __syncthreads();

    // ---- deferred V staging ----
    for (int i = t; i < CHUNK * 16; i += 256) {
        int j = i >> 4, c = i & 15;
        ((float4*)KV)[i] =
            ((const float4*)V)[(((size_t)(b * LL + key0 + j) * HH + h) << 4) + c];
    }
    __syncthreads();

    // ---- phase 2: O = P @ V via FFMA2 ----
    {
        int ublk = t >> 5;
        int d4   = t & 15;
        int jh   = (t >> 4) & 1;
        unsigned long long acc[5][2];
#pragma unroll
        for (int k = 0; k < 5; k++) { acc[k][0] = 0ull; acc[k][1] = 0ull; }
        const ulonglong2* Vs2 = (const ulonglong2*)KV;
        int j0 = jh * 64;
#pragma unroll 4
        for (int jj = 0; jj < 64; jj += 4) {
            int j = j0 + jj;
            ulonglong2 vv0 = Vs2[(j + 0) * 16 + d4];
            ulonglong2 vv1 = Vs2[(j + 1) * 16 + d4];
            ulonglong2 vv2 = Vs2[(j + 2) * 16 + d4];
            ulonglong2 vv3 = Vs2[(j + 3) * 16 + d4];
#pragma unroll
            for (int k = 0; k < 5; k++) {
                float4 p = *(const float4*)(Ss + (ublk * 5 + k) * CHUNK + j);
                unsigned long long p0 = pk2(p.x, p.x);
                unsigned long long p1 = pk2(p.y, p.y);
                unsigned long long p2 = pk2(p.z, p.z);
                unsigned long long p3 = pk2(p.w, p.w);
                acc[k][0] = ffma2(p0, vv0.x, acc[k][0]);
                acc[k][1] = ffma2(p0, vv0.y, acc[k][1]);
                acc[k][0] = ffma2(p1, vv1.x, acc[k][0]);
                acc[k][1] = ffma2(p1, vv1.y, acc[k][1]);
                acc[k][0] = ffma2(p2, vv2.x, acc[k][0]);
                acc[k][1] = ffma2(p2, vv2.y, acc[k][1]);
                acc[k][0] = ffma2(p3, vv3.x, acc[k][0]);
                acc[k][1] = ffma2(p3, vv3.y, acc[k][1]);
            }
        }
        __syncthreads();
#pragma unroll
        for (int k = 0; k < 5; k++) {
            int u = ublk * 5 + k;
            ulonglong2 ov;
            ov.x = acc[k][0];
            ov.y = acc[k][1];
            *(ulonglong2*)(Ss + (jh * NT + u) * 64 + (d4 << 2)) = ov;
        }
    }
    __syncthreads();

    {
        const float4* Ss4 = (const float4*)Ss;
        float4* po4 = (float4*)(g_po + (size_t)(bh * NSPLIT + split) * NT * DD);
        for (int i = t; i < NT * 16; i += 256) {
            float4 a = Ss4[i];
            float4 c = Ss4[NT * 16 + i];
            a.x += c.x; a.y += c.y; a.z += c.z; a.w += c.w;
            po4[i] = a;
        }
    }

    // ---- fused combine: last split-block of this bh ----
    __syncthreads();
    __threadfence();
    if (t == 0)
        s_last = (atomicAdd(&g_cnt2[bh], 1) == NSPLIT - 1) ? 1 : 0;
    __syncthreads();
    if (!s_last) return;

    float* sw = smem;
    float* sl = smem + 640;
    if (t < NT) {
        float m = -3e38f;
#pragma unroll
        for (int s = 0; s < NSPLIT; s++)
            m = fmaxf(m, g_pm[(bh * NSPLIT + s) * NT + t]);
        float Ls = 0.f;
#pragma unroll
        for (int s = 0; s < NSPLIT; s++) {
            float w = __expf(g_pm[(bh * NSPLIT + s) * NT + t] - m);
            sw[t * NSPLIT + s] = w;
            Ls += g_pl[(bh * NSPLIT + s) * NT + t] * w;
        }
        sl[t] = Ls;
    }
    __syncthreads();
    for (int i = t; i < NT * DD; i += 256) {
        int u = i >> 6, d = i & 63;
        float acc = 0.f;
#pragma unroll
        for (int s = 0; s < NSPLIT; s++)
            acc += sw[u * NSPLIT + s] *
                   g_po[(size_t)(bh * NSPLIT + s) * NT * DD + i];
        out[(((size_t)(b * NT + u) * HH + h) << 6) + d] = acc / sl[u];
    }
    __syncthreads();
    if (t == 0) {
        g_cnt2[bh] = 0;
        g_topdone[bh] = 0;
    }
}

// ---------------- launcher: 1 kernel ----------------
extern "C" void kernel_launch(void* const* d_in, const int* in_sizes, int n_in,
                              void* d_out, int out_size) {
    const float* Q   = (const float*)d_in[0];
    const float* K   = (const float*)d_in[1];
    const float* V   = (const float*)d_in[2];
    const void*  idx = d_in[3];

    size_t smemD = (size_t)(NT * DD + 64 * KTPAD + NT * CHUNK) * sizeof(float); // 64512
    cudaFuncSetAttribute(fused_kernel, cudaFuncAttributeMaxDynamicSharedMemorySize, (int)smemD);
    fused_kernel<<<NSAMPBLK + NATTNBLK, 256, smemD>>>(Q, K, V, idx, (float*)d_out);
}